// round 1
// baseline (speedup 1.0000x reference)
#include <cuda_runtime.h>
#include <cstdint>

#define B_  8
#define C_  128
#define H_  192
#define W_  448
#define ND  49

#define TX  32          // tile pixels in x
#define TY  16          // tile pixels in y
#define KC  8           // channels per chunk
#define NCHUNK (C_ / KC)

#define S1_ROW 32                 // floats per row, first tile
#define S2_ROW 44                 // padded row: logical x in [-4, TX+7] -> idx = x+4
#define S1_CH  (TY * S1_ROW)      // 512
#define S2_CH  ((TY + 6) * S2_ROW)// 22*44 = 968
#define S1_SIZE (KC * S1_CH)      // 4096 floats
#define S2_SIZE (KC * S2_CH)      // 7744 floats
#define BUF_SIZE (S1_SIZE + S2_SIZE)  // 11840 floats
#define SMEM_BYTES (2 * BUF_SIZE * sizeof(float))  // 94720 B

__device__ __forceinline__ uint32_t sptr(const void* p) {
    return (uint32_t)__cvta_generic_to_shared(p);
}
__device__ __forceinline__ void cp16(void* dst, const float* src, bool pred) {
    int bytes = pred ? 16 : 0;
    asm volatile("cp.async.cg.shared.global [%0], [%1], 16, %2;\n"
                 :: "r"(sptr(dst)), "l"(src), "r"(bytes));
}
__device__ __forceinline__ void cp4(void* dst, const float* src, bool pred) {
    int bytes = pred ? 4 : 0;
    asm volatile("cp.async.ca.shared.global [%0], [%1], 4, %2;\n"
                 :: "r"(sptr(dst)), "l"(src), "r"(bytes));
}
__device__ __forceinline__ void cp_commit() {
    asm volatile("cp.async.commit_group;\n" ::: "memory");
}

__device__ __forceinline__ void load_chunk(
    float* __restrict__ s1, float* __restrict__ s2,
    const float* __restrict__ fbase, const float* __restrict__ sbase,
    int c0, int x0, int y0, int tid)
{
    const size_t HW = (size_t)H_ * W_;
    // ---- first tile: 8ch x 16 rows x 8 float4 = 1024 units ----
#pragma unroll
    for (int it = 0; it < 8; ++it) {
        int u = tid + it * 128;
        int c = u >> 7;
        int rem = u & 127;
        int row = rem >> 3;
        int q = rem & 7;
        const float* src = fbase + (size_t)(c0 + c) * HW + (size_t)(y0 + row) * W_ + x0 + q * 4;
        cp16(s1 + c * S1_CH + row * S1_ROW + q * 4, src, true);
    }
    // ---- second interior: 8ch x 22 rows x 8 float4 = 1408 units ----
#pragma unroll
    for (int it = 0; it < 11; ++it) {
        int u = tid + it * 128;
        int c = u / 176;
        int rem = u - c * 176;
        int row = rem >> 3;
        int q = rem & 7;
        int gy = y0 - 3 + row;
        bool p = (gy >= 0) && (gy < H_);
        int gyc = gy < 0 ? 0 : (gy >= H_ ? H_ - 1 : gy);
        const float* src = sbase + (size_t)(c0 + c) * HW + (size_t)gyc * W_ + x0 + q * 4;
        cp16(s2 + c * S2_CH + row * S2_ROW + 4 + q * 4, src, p);
    }
    // ---- second edges: 8ch x 22 rows x 6 scalars = 1056 units ----
#pragma unroll
    for (int it = 0; it < 9; ++it) {
        int u = tid + it * 128;
        if (u < 1056) {
            int c = u / 132;
            int rem = u - c * 132;
            int row = rem / 6;
            int e = rem - row * 6;
            int x = (e < 3) ? (e - 3) : (TX + e - 3);   // -3,-2,-1, 32,33,34
            int gy = y0 - 3 + row;
            int gx = x0 + x;
            bool p = (gy >= 0) && (gy < H_) && (gx >= 0) && (gx < W_);
            int gyc = gy < 0 ? 0 : (gy >= H_ ? H_ - 1 : gy);
            int gxc = gx < 0 ? 0 : (gx >= W_ ? W_ - 1 : gx);
            const float* src = sbase + (size_t)(c0 + c) * HW + (size_t)gyc * W_ + gxc;
            cp4(s2 + c * S2_CH + row * S2_ROW + (x + 4), src, p);
        }
    }
}

__global__ void __launch_bounds__(128, 2)
corr_kernel(const float* __restrict__ first,
            const float* __restrict__ second,
            float* __restrict__ out)
{
    extern __shared__ float smem[];
    const int tid = threadIdx.x;
    const int bx = blockIdx.x, by = blockIdx.y, b = blockIdx.z;
    const int x0 = bx * TX, y0 = by * TY;
    const int txl = tid & 7;      // 0..7, owns 4 x-pixels
    const int tyl = tid >> 3;     // 0..15, one y-row

    const size_t HW = (size_t)H_ * W_;
    const float* fbase = first  + (size_t)b * C_ * HW;
    const float* sbase = second + (size_t)b * C_ * HW;

    float acc[ND][4];
#pragma unroll
    for (int d = 0; d < ND; ++d)
#pragma unroll
        for (int p = 0; p < 4; ++p)
            acc[d][p] = 0.0f;

    // prologue: load chunk 0 into buffer 0
    load_chunk(smem, smem + S1_SIZE, fbase, sbase, 0, x0, y0, tid);
    cp_commit();

#pragma unroll 1
    for (int k = 0; k < NCHUNK; ++k) {
        if (k < NCHUNK - 1) {
            float* nb = smem + ((k + 1) & 1) * BUF_SIZE;
            load_chunk(nb, nb + S1_SIZE, fbase, sbase, (k + 1) * KC, x0, y0, tid);
            cp_commit();
            asm volatile("cp.async.wait_group 1;\n" ::: "memory");
        } else {
            asm volatile("cp.async.wait_group 0;\n" ::: "memory");
        }
        __syncthreads();

        const float* s1 = smem + (k & 1) * BUF_SIZE;
        const float* s2 = s1 + S1_SIZE;

#pragma unroll 1
        for (int c = 0; c < KC; ++c) {
            float4 f = *(const float4*)(s1 + c * S1_CH + tyl * S1_ROW + txl * 4);
#pragma unroll
            for (int rr = 0; rr < 7; ++rr) {
                const float* vp = s2 + c * S2_CH + (tyl + rr) * S2_ROW + txl * 4;
                float4 v0 = ((const float4*)vp)[0];
                float4 v1 = ((const float4*)vp)[1];
                float4 v2 = ((const float4*)vp)[2];
                float v[12] = { v0.x, v0.y, v0.z, v0.w,
                                v1.x, v1.y, v1.z, v1.w,
                                v2.x, v2.y, v2.z, v2.w };
#pragma unroll
                for (int di = 0; di < 7; ++di) {
                    acc[rr * 7 + di][0] += f.x * v[di + 1];
                    acc[rr * 7 + di][1] += f.y * v[di + 2];
                    acc[rr * 7 + di][2] += f.z * v[di + 3];
                    acc[rr * 7 + di][3] += f.w * v[di + 4];
                }
            }
        }
        __syncthreads();
    }

    // epilogue: mean over channels, write [B, 49, H, W]
    const float invC = 1.0f / (float)C_;
    const int y = y0 + tyl;
    const int x = x0 + txl * 4;
    float* obase = out + ((size_t)b * ND * H_ + (size_t)y) * 0; // dummy to keep compiler honest
    (void)obase;
#pragma unroll
    for (int d = 0; d < ND; ++d) {
        float4 o;
        o.x = acc[d][0] * invC;
        o.y = acc[d][1] * invC;
        o.z = acc[d][2] * invC;
        o.w = acc[d][3] * invC;
        *(float4*)(out + (((size_t)b * ND + d) * H_ + y) * W_ + x) = o;
    }
}

extern "C" void kernel_launch(void* const* d_in, const int* in_sizes, int n_in,
                              void* d_out, int out_size)
{
    const float* first  = (const float*)d_in[0];
    const float* second = (const float*)d_in[1];
    float* out = (float*)d_out;

    cudaFuncSetAttribute(corr_kernel,
                         cudaFuncAttributeMaxDynamicSharedMemorySize,
                         (int)SMEM_BYTES);

    dim3 grid(W_ / TX, H_ / TY, B_);   // 14 x 12 x 8 = 1344 CTAs
    dim3 block(128);
    corr_kernel<<<grid, block, SMEM_BYTES>>>(first, second, out);
}

// round 2
// speedup vs baseline: 1.7321x; 1.7321x over previous
#include <cuda_runtime.h>
#include <cstdint>

#define B_  8
#define C_  128
#define H_  192
#define W_  448
#define ND  49

#define TX  32
#define TY  16
#define KC  8
#define NCHUNK (C_ / KC)
#define NT  256

#define S1_ROW 32
#define S2_ROW 44
#define S1_CH  (TY * S1_ROW)        // 512
#define S2_CH  ((TY + 6) * S2_ROW)  // 968
#define S1_SIZE (KC * S1_CH)        // 4096
#define S2_SIZE (KC * S2_CH)        // 7744
#define BUF_SIZE (S1_SIZE + S2_SIZE)
#define SMEM_BYTES (2 * BUF_SIZE * sizeof(float))  // 94720 B

__device__ __forceinline__ uint32_t sptr(const void* p) {
    return (uint32_t)__cvta_generic_to_shared(p);
}
__device__ __forceinline__ void cp16(void* dst, const float* src, bool pred) {
    int bytes = pred ? 16 : 0;
    asm volatile("cp.async.cg.shared.global [%0], [%1], 16, %2;\n"
                 :: "r"(sptr(dst)), "l"(src), "r"(bytes));
}
__device__ __forceinline__ void cp4(void* dst, const float* src, bool pred) {
    int bytes = pred ? 4 : 0;
    asm volatile("cp.async.ca.shared.global [%0], [%1], 4, %2;\n"
                 :: "r"(sptr(dst)), "l"(src), "r"(bytes));
}
__device__ __forceinline__ void cp_commit() {
    asm volatile("cp.async.commit_group;\n" ::: "memory");
}

__device__ __forceinline__ void load_chunk(
    float* __restrict__ s1, float* __restrict__ s2,
    const float* __restrict__ fbase, const float* __restrict__ sbase,
    int c0, int x0, int y0, int tid)
{
    const size_t HW = (size_t)H_ * W_;
    // ---- first tile: 8ch x 16 rows x 8 float4 = 1024 units (4 iters @256) ----
#pragma unroll
    for (int it = 0; it < 4; ++it) {
        int u = tid + it * NT;
        int c = u >> 7;
        int rem = u & 127;
        int row = rem >> 3;
        int q = rem & 7;
        const float* src = fbase + (size_t)(c0 + c) * HW + (size_t)(y0 + row) * W_ + x0 + q * 4;
        cp16(s1 + c * S1_CH + row * S1_ROW + q * 4, src, true);
    }
    // ---- second interior: 8ch x 22 rows x 8 float4 = 1408 units ----
#pragma unroll
    for (int it = 0; it < 6; ++it) {
        int u = tid + it * NT;
        if (it < 5 || u < 1408) {
            int c = u / 176;
            int rem = u - c * 176;
            int row = rem >> 3;
            int q = rem & 7;
            int gy = y0 - 3 + row;
            bool p = (gy >= 0) && (gy < H_);
            int gyc = gy < 0 ? 0 : (gy >= H_ ? H_ - 1 : gy);
            const float* src = sbase + (size_t)(c0 + c) * HW + (size_t)gyc * W_ + x0 + q * 4;
            cp16(s2 + c * S2_CH + row * S2_ROW + 4 + q * 4, src, p);
        }
    }
    // ---- second edges: 8ch x 22 rows x 6 scalars = 1056 units ----
#pragma unroll
    for (int it = 0; it < 5; ++it) {
        int u = tid + it * NT;
        if (it < 4 || u < 1056) {
            int c = u / 132;
            int rem = u - c * 132;
            int row = rem / 6;
            int e = rem - row * 6;
            int x = (e < 3) ? (e - 3) : (TX + e - 3);
            int gy = y0 - 3 + row;
            int gx = x0 + x;
            bool p = (gy >= 0) && (gy < H_) && (gx >= 0) && (gx < W_);
            int gyc = gy < 0 ? 0 : (gy >= H_ ? H_ - 1 : gy);
            int gxc = gx < 0 ? 0 : (gx >= W_ ? W_ - 1 : gx);
            const float* src = sbase + (size_t)(c0 + c) * HW + (size_t)gyc * W_ + gxc;
            cp4(s2 + c * S2_CH + row * S2_ROW + (x + 4), src, p);
        }
    }
}

// Accumulate flattened displacements d in [D0, D1) for one channel chunk.
// acc index is (d - D0). All di bounds fold at compile time under full unroll.
template<int D0, int D1>
__device__ __forceinline__ void accumulate(
    const float* __restrict__ s1, const float* __restrict__ s2,
    int tyl, int txl, float (&acc)[25][4])
{
    constexpr int RR0 = D0 / 7;
    constexpr int RR1 = (D1 - 1) / 7 + 1;

#pragma unroll 1
    for (int c = 0; c < KC; ++c) {
        float4 f = *(const float4*)(s1 + c * S1_CH + tyl * S1_ROW + txl * 4);
#pragma unroll
        for (int rr = RR0; rr < RR1; ++rr) {
            const int di0 = (rr * 7 < D0) ? (D0 - rr * 7) : 0;
            const int di1 = (rr * 7 + 7 > D1) ? (D1 - rr * 7) : 7;
            const float* vp = s2 + c * S2_CH + (tyl + rr) * S2_ROW + txl * 4;
            float4 v0 = ((const float4*)vp)[0];
            float4 v1 = ((const float4*)vp)[1];
            float4 v2 = ((const float4*)vp)[2];
            float v[12] = { v0.x, v0.y, v0.z, v0.w,
                            v1.x, v1.y, v1.z, v1.w,
                            v2.x, v2.y, v2.z, v2.w };
#pragma unroll
            for (int di = di0; di < di1; ++di) {
                const int a = rr * 7 + di - D0;
                acc[a][0] += f.x * v[di + 1];
                acc[a][1] += f.y * v[di + 2];
                acc[a][2] += f.z * v[di + 3];
                acc[a][3] += f.w * v[di + 4];
            }
        }
    }
}

template<int D0, int D1>
__device__ __forceinline__ void epilogue(
    float* __restrict__ out, const float (&acc)[25][4],
    int b, int y, int x)
{
    const float invC = 1.0f / (float)C_;
#pragma unroll
    for (int d = D0; d < D1; ++d) {
        const int a = d - D0;
        float4 o;
        o.x = acc[a][0] * invC;
        o.y = acc[a][1] * invC;
        o.z = acc[a][2] * invC;
        o.w = acc[a][3] * invC;
        *(float4*)(out + (((size_t)b * ND + d) * H_ + y) * W_ + x) = o;
    }
}

__global__ void __launch_bounds__(NT, 1)
corr_kernel(const float* __restrict__ first,
            const float* __restrict__ second,
            float* __restrict__ out)
{
    extern __shared__ float smem[];
    const int tid = threadIdx.x;
    const int wg   = tid >> 7;        // warpgroup 0 or 1
    const int wtid = tid & 127;
    const int bx = blockIdx.x, by = blockIdx.y, b = blockIdx.z;
    const int x0 = bx * TX, y0 = by * TY;
    const int txl = wtid & 7;         // 0..7, owns 4 x-pixels
    const int tyl = wtid >> 3;        // 0..15, one y-row

    const size_t HW = (size_t)H_ * W_;
    const float* fbase = first  + (size_t)b * C_ * HW;
    const float* sbase = second + (size_t)b * C_ * HW;

    float acc[25][4];
#pragma unroll
    for (int d = 0; d < 25; ++d)
#pragma unroll
        for (int p = 0; p < 4; ++p)
            acc[d][p] = 0.0f;

    load_chunk(smem, smem + S1_SIZE, fbase, sbase, 0, x0, y0, tid);
    cp_commit();

#pragma unroll 1
    for (int k = 0; k < NCHUNK; ++k) {
        if (k < NCHUNK - 1) {
            float* nb = smem + ((k + 1) & 1) * BUF_SIZE;
            load_chunk(nb, nb + S1_SIZE, fbase, sbase, (k + 1) * KC, x0, y0, tid);
            cp_commit();
            asm volatile("cp.async.wait_group 1;\n" ::: "memory");
        } else {
            asm volatile("cp.async.wait_group 0;\n" ::: "memory");
        }
        __syncthreads();

        const float* s1 = smem + (k & 1) * BUF_SIZE;
        const float* s2 = s1 + S1_SIZE;

        if (wg == 0) accumulate<0, 24>(s1, s2, tyl, txl, acc);
        else         accumulate<24, 49>(s1, s2, tyl, txl, acc);

        __syncthreads();
    }

    const int y = y0 + tyl;
    const int x = x0 + txl * 4;
    if (wg == 0) epilogue<0, 24>(out, acc, b, y, x);
    else         epilogue<24, 49>(out, acc, b, y, x);
}

extern "C" void kernel_launch(void* const* d_in, const int* in_sizes, int n_in,
                              void* d_out, int out_size)
{
    const float* first  = (const float*)d_in[0];
    const float* second = (const float*)d_in[1];
    float* out = (float*)d_out;

    cudaFuncSetAttribute(corr_kernel,
                         cudaFuncAttributeMaxDynamicSharedMemorySize,
                         (int)SMEM_BYTES);

    dim3 grid(W_ / TX, H_ / TY, B_);   // 14 x 12 x 8 = 1344 CTAs
    dim3 block(NT);
    corr_kernel<<<grid, block, SMEM_BYTES>>>(first, second, out);
}